// round 1
// baseline (speedup 1.0000x reference)
#include <cuda_runtime.h>
#include <cstdint>
#include <cstddef>

#define NB 1024
#define NT 512
#define NH 128
#define NG 512   // 4*H

// ---------------- scratch (device globals; no runtime allocation) ----------------
__device__ float g_h0[(size_t)NB * NT * NH];   // layer0 output  [B][T][H]
__device__ float g_h1[(size_t)NB * NT * NH];   // layer1 output  [B][T][H]
__device__ float g_hlast[NB * NH];             // layer2 last-step h
__device__ float g_WT[3][256 * NG];            // per layer: [k][u][4] (i,f,g,o packed)
__device__ float g_bias[3][NG];                // per layer: [u][4]

// ---------------- weight transpose / pack ----------------
// WT[k][u][q] = (k < din) ? w_ih[q*H+u][k] : w_hh[q*H+u][k-din];  zeros for k >= din+H (pad rows)
__global__ void prep_kernel(const float* __restrict__ w_ih, const float* __restrict__ w_hh,
                            const float* __restrict__ b_ih, const float* __restrict__ b_hh,
                            int layer, int din, int kp)
{
    float* WT = g_WT[layer];
    int total = kp * NG;
    for (int idx = blockIdx.x * blockDim.x + threadIdx.x; idx < total;
         idx += gridDim.x * blockDim.x) {
        int q = idx & 3;
        int u = (idx >> 2) & (NH - 1);
        int k = idx >> 9;
        int g = q * NH + u;
        float val = 0.0f;
        if (k < din)            val = w_ih[g * din + k];
        else if (k < din + NH)  val = w_hh[g * NH + (k - din)];
        WT[idx] = val;
    }
    for (int g = blockIdx.x * blockDim.x + threadIdx.x; g < NG;
         g += gridDim.x * blockDim.x) {
        int q = g / NH, u = g % NH;
        g_bias[layer][u * 4 + q] = b_ih[g] + b_hh[g];
    }
}

// ---------------- activations (HW MUFU.TANH) ----------------
__device__ __forceinline__ float fast_tanh(float x) {
    float y;
    asm("tanh.approx.f32 %0, %1;" : "=f"(y) : "f"(x));
    return y;
}
__device__ __forceinline__ float fast_sig(float x) {
    return fmaf(0.5f, fast_tanh(0.5f * x), 0.5f);
}

#define ACC4(j, xv)                                                                     \
    acc[j][0] = fmaf(w0.x, xv.x, fmaf(w1.x, xv.y, fmaf(w2.x, xv.z, fmaf(w3.x, xv.w, acc[j][0])))); \
    acc[j][1] = fmaf(w0.y, xv.x, fmaf(w1.y, xv.y, fmaf(w2.y, xv.z, fmaf(w3.y, xv.w, acc[j][1])))); \
    acc[j][2] = fmaf(w0.z, xv.x, fmaf(w1.z, xv.y, fmaf(w2.z, xv.z, fmaf(w3.z, xv.w, acc[j][2])))); \
    acc[j][3] = fmaf(w0.w, xv.x, fmaf(w1.w, xv.y, fmaf(w2.w, xv.z, fmaf(w3.w, xv.w, acc[j][3]))));

// ---------------- LSTM layer: one CTA = 8 batch rows, loops all T internally ------
// thread tile: unit u = tid&127, batch-half bh = tid>>7 -> 4 gates x 4 batches accums
template <int DIN>
__global__ void __launch_bounds__(256, 1)
lstm_layer_kernel(const float* __restrict__ xin,  // [B][T][DIN]
                  float* __restrict__ hout,       // [B][T][H] or nullptr
                  float* __restrict__ hlast,      // [B][H]   or nullptr
                  int layer)
{
    constexpr int K  = DIN + NH;
    constexpr int KP = (K + 3) & ~3;      // 136 (layer0) / 256 (layers 1,2)
    __shared__ __align__(16) float v[8][KP];   // [batch][k] : x part + h part

    const float4* __restrict__ WT4 = reinterpret_cast<const float4*>(g_WT[layer]);

    const int tid = threadIdx.x;
    const int u   = tid & (NH - 1);
    const int bh  = tid >> 7;             // 0 or 1
    const int b0  = blockIdx.x * 8;
    const int bb  = b0 + bh * 4;

    const float4 bias4 = *reinterpret_cast<const float4*>(&g_bias[layer][u * 4]);

    // zero v (h part must start at 0; pad cols stay 0 forever)
    for (int i = tid; i < 8 * KP; i += 256) (&v[0][0])[i] = 0.0f;

    float c[4] = {0.f, 0.f, 0.f, 0.f};

    const float* vb0 = v[bh * 4 + 0];
    const float* vb1 = v[bh * 4 + 1];
    const float* vb2 = v[bh * 4 + 2];
    const float* vb3 = v[bh * 4 + 3];

    for (int t = 0; t < NT; ++t) {
        // ---- stage x_t into v[b][0:DIN] (coalesced global read) ----
        if (DIN == 128) {
            int b  = tid >> 5;
            int k4 = (tid & 31) * 4;
            float4 xv = *reinterpret_cast<const float4*>(
                &xin[((size_t)(b0 + b) * NT + t) * DIN + k4]);
            *reinterpret_cast<float4*>(&v[b][k4]) = xv;
        } else {
            if (tid < 8 * DIN) {
                int b = tid / DIN;
                int k = tid - b * DIN;
                v[b][k] = xin[((size_t)(b0 + b) * NT + t) * DIN + k];
            }
        }
        __syncthreads();

        // ---- gates = bias + W * [x_t ; h_{t-1}] ----
        float acc[4][4];
#pragma unroll
        for (int j = 0; j < 4; ++j) {
            acc[j][0] = bias4.x; acc[j][1] = bias4.y;
            acc[j][2] = bias4.z; acc[j][3] = bias4.w;
        }

#pragma unroll 2
        for (int k = 0; k < KP; k += 4) {
            float4 w0 = WT4[(size_t)(k + 0) * NH + u];
            float4 w1 = WT4[(size_t)(k + 1) * NH + u];
            float4 w2 = WT4[(size_t)(k + 2) * NH + u];
            float4 w3 = WT4[(size_t)(k + 3) * NH + u];
            float4 x0 = *reinterpret_cast<const float4*>(vb0 + k);
            float4 x1 = *reinterpret_cast<const float4*>(vb1 + k);
            float4 x2 = *reinterpret_cast<const float4*>(vb2 + k);
            float4 x3 = *reinterpret_cast<const float4*>(vb3 + k);
            ACC4(0, x0)
            ACC4(1, x1)
            ACC4(2, x2)
            ACC4(3, x3)
        }

        // ---- pointwise LSTM cell ----
        float hn[4];
#pragma unroll
        for (int j = 0; j < 4; ++j) {
            float ii = fast_sig(acc[j][0]);
            float ff = fast_sig(acc[j][1]);
            float gg = fast_tanh(acc[j][2]);
            float oo = fast_sig(acc[j][3]);
            float cn = fmaf(ff, c[j], ii * gg);
            c[j] = cn;
            hn[j] = oo * fast_tanh(cn);
        }
        __syncthreads();   // all reads of v done before overwrite

#pragma unroll
        for (int j = 0; j < 4; ++j) v[bh * 4 + j][DIN + u] = hn[j];

        if (hout) {
#pragma unroll
            for (int j = 0; j < 4; ++j)
                hout[((size_t)(bb + j) * NT + t) * NH + u] = hn[j];
        }
        if (hlast && t == NT - 1) {
#pragma unroll
            for (int j = 0; j < 4; ++j)
                hlast[(bb + j) * NH + u] = hn[j];
        }
    }
}

// ---------------- final FC on last timestep of layer 2 ----------------
__global__ void fc_kernel(const float* __restrict__ fc_w,
                          const float* __restrict__ fc_b,
                          float* __restrict__ out)
{
    int b = blockIdx.x;
    int tid = threadIdx.x;           // 128 threads, one per unit
    float p = g_hlast[b * NH + tid] * fc_w[tid];
#pragma unroll
    for (int o = 16; o; o >>= 1) p += __shfl_down_sync(0xffffffffu, p, o);
    __shared__ float ws[4];
    if ((tid & 31) == 0) ws[tid >> 5] = p;
    __syncthreads();
    if (tid == 0) out[b] = ws[0] + ws[1] + ws[2] + ws[3] + fc_b[0];
}

// ---------------- launch ----------------
extern "C" void kernel_launch(void* const* d_in, const int* in_sizes, int n_in,
                              void* d_out, int out_size)
{
    const float* x    = (const float*)d_in[0];
    const float* wih0 = (const float*)d_in[1];
    const float* whh0 = (const float*)d_in[2];
    const float* bih0 = (const float*)d_in[3];
    const float* bhh0 = (const float*)d_in[4];
    const float* wih1 = (const float*)d_in[5];
    const float* whh1 = (const float*)d_in[6];
    const float* bih1 = (const float*)d_in[7];
    const float* bhh1 = (const float*)d_in[8];
    const float* wih2 = (const float*)d_in[9];
    const float* whh2 = (const float*)d_in[10];
    const float* bih2 = (const float*)d_in[11];
    const float* bhh2 = (const float*)d_in[12];
    const float* fcw  = (const float*)d_in[13];
    const float* fcb  = (const float*)d_in[14];
    float* out = (float*)d_out;

    void *ph0 = nullptr, *ph1 = nullptr, *phl = nullptr;
    cudaGetSymbolAddress(&ph0, g_h0);
    cudaGetSymbolAddress(&ph1, g_h1);
    cudaGetSymbolAddress(&phl, g_hlast);

    prep_kernel<<<132, 256>>>(wih0, whh0, bih0, bhh0, 0, 6,   136);
    prep_kernel<<<132, 256>>>(wih1, whh1, bih1, bhh1, 1, 128, 256);
    prep_kernel<<<132, 256>>>(wih2, whh2, bih2, bhh2, 2, 128, 256);

    lstm_layer_kernel<6>  <<<NB / 8, 256>>>(x, (float*)ph0, nullptr, 0);
    lstm_layer_kernel<128><<<NB / 8, 256>>>((const float*)ph0, (float*)ph1, nullptr, 1);
    lstm_layer_kernel<128><<<NB / 8, 256>>>((const float*)ph1, nullptr, (float*)phl, 2);

    fc_kernel<<<NB, 128>>>(fcw, fcb, out);
}